// round 2
// baseline (speedup 1.0000x reference)
#include <cuda_runtime.h>
#include <cuda_bf16.h>
#include <math.h>

#define NB 8192
#define NC 32000

// per-row loss scratch (device global: allocation-free)
__device__ float g_row_loss[NB];

__inline__ __device__ float warpReduceSum(float v) {
#pragma unroll
    for (int o = 16; o > 0; o >>= 1)
        v += __shfl_down_sync(0xffffffffu, v, o);
    return v;
}

__global__ __launch_bounds__(256) void row_loss_kernel(
    const float* __restrict__ y_pred,
    const int* __restrict__ y_true)   // JAX x64-disabled: int64 request degrades to int32
{
    const int row = blockIdx.x;
    const float* rowp = y_pred + (size_t)row * NC;
    const float4* p4 = reinterpret_cast<const float4*>(rowp);
    const int n4 = NC / 4;  // 8000

    float s = 0.0f;
#pragma unroll 4
    for (int i = threadIdx.x; i < n4; i += 256) {
        float4 v = __ldg(p4 + i);
        s += __expf(v.x) + __expf(v.y) + __expf(v.z) + __expf(v.w);
    }

    // block reduce
    __shared__ float sh[8];
    const int lane = threadIdx.x & 31;
    const int wid  = threadIdx.x >> 5;
    s = warpReduceSum(s);
    if (lane == 0) sh[wid] = s;
    __syncthreads();
    if (wid == 0) {
        float v = (lane < 8) ? sh[lane] : 0.0f;
        v = warpReduceSum(v);
        if (lane == 0) {
            int t = y_true[row];
            // crash guard (should never trigger if dtype guess is right)
            t = (t < 0) ? 0 : ((t >= NC) ? NC - 1 : t);
            const float pt = __ldg(rowp + t);
            const float et = __expf(pt);
            const float sneg = v - et;           // sum over negatives
            g_row_loss[row] = log1pf(sneg * __expf(-pt));
        }
    }
}

__global__ __launch_bounds__(1024) void mean_kernel(float* __restrict__ out)
{
    double s = 0.0;
    for (int i = threadIdx.x; i < NB; i += 1024)
        s += (double)g_row_loss[i];

    __shared__ double sh[32];
    const int lane = threadIdx.x & 31;
    const int wid  = threadIdx.x >> 5;
#pragma unroll
    for (int o = 16; o > 0; o >>= 1)
        s += __shfl_down_sync(0xffffffffu, s, o);
    if (lane == 0) sh[wid] = s;
    __syncthreads();
    if (wid == 0) {
        double v = (lane < 32) ? sh[lane] : 0.0;
#pragma unroll
        for (int o = 16; o > 0; o >>= 1)
            v += __shfl_down_sync(0xffffffffu, v, o);
        if (lane == 0)
            out[0] = (float)(v / (double)NB);
    }
}

extern "C" void kernel_launch(void* const* d_in, const int* in_sizes, int n_in,
                              void* d_out, int out_size)
{
    const float* y_pred = (const float*)d_in[0];
    const int*   y_true = (const int*)d_in[1];
    float* out = (float*)d_out;

    row_loss_kernel<<<NB, 256>>>(y_pred, y_true);
    mean_kernel<<<1, 1024>>>(out);
}